// round 1
// baseline (speedup 1.0000x reference)
#include <cuda_runtime.h>
#include <math.h>

#define N_    8
#define C_    256
#define H_    64
#define W_    64
#define KH_   3
#define KW_   3
#define K_    9
#define HO_   64
#define WO_   64
#define P_    4096          // HO_*WO_
#define CK_   2304          // C_*K_
#define COUT_ 256

// scratch: cols[n][c*9+k][p]  (302 MB, device global -> no runtime alloc)
__device__ float g_cols[(size_t)N_ * CK_ * P_];

// ---------------------------------------------------------------------------
// Kernel 1: deformable im2col (bilinear sampling)
// one thread per (n, k, p); loops over all 256 channels reusing the 4 corner
// indices + weights. Stores are fully coalesced over p.
// ---------------------------------------------------------------------------
__global__ void im2col_k(const float* __restrict__ x,
                         const float* __restrict__ off)
{
    int idx = blockIdx.x * blockDim.x + threadIdx.x;
    if (idx >= N_ * K_ * P_) return;

    int p  = idx & (P_ - 1);
    int nk = idx >> 12;           // P_ = 4096 = 2^12
    int k  = nk % K_;
    int n  = nk / K_;
    int ho = p >> 6;              // WO_=64
    int wo = p & 63;
    int ky = k / 3;
    int kx = k % 3;

    // offset layout: [N, K, 2(y,x), Ho, Wo]  (DG=1)
    const float* ob = off + ((size_t)n * (2 * K_) + k * 2) * P_;
    float py = (float)(ho - 1 + ky) + ob[p];        // stride 1, pad 1, dil 1
    float px = (float)(wo - 1 + kx) + ob[P_ + p];

    float y0f = floorf(py), x0f = floorf(px);
    float ly = py - y0f, lx = px - x0f;
    float hy = 1.0f - ly, hx = 1.0f - lx;
    int y0 = (int)y0f, x0 = (int)x0f;
    int y1 = y0 + 1,   x1 = x0 + 1;

    bool vy0 = ((unsigned)y0 < (unsigned)H_);
    bool vy1 = ((unsigned)y1 < (unsigned)H_);
    bool vx0 = ((unsigned)x0 < (unsigned)W_);
    bool vx1 = ((unsigned)x1 < (unsigned)W_);

    int cy0 = min(max(y0, 0), H_ - 1);
    int cy1 = min(max(y1, 0), H_ - 1);
    int cx0 = min(max(x0, 0), W_ - 1);
    int cx1 = min(max(x1, 0), W_ - 1);

    float w00 = (vy0 && vx0) ? hy * hx : 0.0f;
    float w01 = (vy0 && vx1) ? hy * lx : 0.0f;
    float w10 = (vy1 && vx0) ? ly * hx : 0.0f;
    float w11 = (vy1 && vx1) ? ly * lx : 0.0f;

    int i00 = cy0 * W_ + cx0;
    int i01 = cy0 * W_ + cx1;
    int i10 = cy1 * W_ + cx0;
    int i11 = cy1 * W_ + cx1;

    const float* xb  = x + (size_t)n * C_ * H_ * W_;
    float*       col = g_cols + ((size_t)n * CK_ + k) * P_ + p;

    #pragma unroll 4
    for (int c = 0; c < C_; ++c) {
        const float* xc = xb + (size_t)c * (H_ * W_);
        float v = w00 * xc[i00] + w01 * xc[i01]
                + w10 * xc[i10] + w11 * xc[i11];
        col[(size_t)c * (K_ * P_)] = v;
    }
}

// ---------------------------------------------------------------------------
// Kernel 2: batched SGEMM  out[n] = W[256,2304] @ cols[n][2304,4096] + bias
// 128x128 tile, BK=8, 256 threads, 8x8 per-thread microtile.
// ---------------------------------------------------------------------------
__global__ __launch_bounds__(256, 2)
void gemm_k(const float* __restrict__ A,      // weight [COUT_, CK_]
            const float* __restrict__ bias,   // [COUT_]
            float* __restrict__ out)          // [N_, COUT_, P_]
{
    __shared__ float As[8][128];   // transposed A tile: As[kk][m]
    __shared__ float Bs[8][128];   // Bs[kk][nn]

    const int n   = blockIdx.z;
    const int bm0 = blockIdx.y * 128;
    const int bn0 = blockIdx.x * 128;

    const float* B = g_cols + (size_t)n * CK_ * P_;

    const int tid   = threadIdx.x;
    const int arow  = tid >> 1;            // 0..127
    const int acol4 = (tid & 1) * 4;       // 0 or 4
    const int brow  = tid >> 5;            // 0..7
    const int bcol4 = (tid & 31) * 4;      // 0..124
    const int tx    = tid & 15;
    const int ty    = tid >> 4;

    float acc[8][8];
    #pragma unroll
    for (int i = 0; i < 8; ++i)
        #pragma unroll
        for (int j = 0; j < 8; ++j) acc[i][j] = 0.0f;

    const float* aptr = A + (size_t)(bm0 + arow) * CK_ + acol4;
    const float* bptr = B + (size_t)brow * P_ + bn0 + bcol4;

    for (int k0 = 0; k0 < CK_; k0 += 8) {
        float4 av = *(const float4*)(aptr + k0);
        float4 bv = *(const float4*)(bptr + (size_t)k0 * P_);

        __syncthreads();   // previous iteration's reads complete
        As[acol4 + 0][arow] = av.x;
        As[acol4 + 1][arow] = av.y;
        As[acol4 + 2][arow] = av.z;
        As[acol4 + 3][arow] = av.w;
        *(float4*)&Bs[brow][bcol4] = bv;
        __syncthreads();

        #pragma unroll
        for (int kk = 0; kk < 8; ++kk) {
            float ar[8], br[8];
            *(float4*)&ar[0] = *(const float4*)&As[kk][ty * 8];
            *(float4*)&ar[4] = *(const float4*)&As[kk][ty * 8 + 4];
            *(float4*)&br[0] = *(const float4*)&Bs[kk][tx * 8];
            *(float4*)&br[4] = *(const float4*)&Bs[kk][tx * 8 + 4];
            #pragma unroll
            for (int i = 0; i < 8; ++i)
                #pragma unroll
                for (int j = 0; j < 8; ++j)
                    acc[i][j] = fmaf(ar[i], br[j], acc[i][j]);
        }
    }

    float* outn = out + (size_t)n * COUT_ * P_;
    #pragma unroll
    for (int i = 0; i < 8; ++i) {
        int co = bm0 + ty * 8 + i;
        float bv = bias[co];
        float4 o0, o1;
        o0.x = acc[i][0] + bv; o0.y = acc[i][1] + bv;
        o0.z = acc[i][2] + bv; o0.w = acc[i][3] + bv;
        o1.x = acc[i][4] + bv; o1.y = acc[i][5] + bv;
        o1.z = acc[i][6] + bv; o1.w = acc[i][7] + bv;
        *(float4*)&outn[(size_t)co * P_ + bn0 + tx * 8]     = o0;
        *(float4*)&outn[(size_t)co * P_ + bn0 + tx * 8 + 4] = o1;
    }
}

// ---------------------------------------------------------------------------
extern "C" void kernel_launch(void* const* d_in, const int* in_sizes, int n_in,
                              void* d_out, int out_size)
{
    const float* x    = (const float*)d_in[0];
    const float* off  = (const float*)d_in[1];
    const float* wgt  = (const float*)d_in[2];
    const float* bias = (const float*)d_in[3];
    float* out = (float*)d_out;

    int total = N_ * K_ * P_;
    im2col_k<<<(total + 255) / 256, 256>>>(x, off);

    dim3 grid(P_ / 128, COUT_ / 128, N_);   // (32, 2, 8)
    gemm_k<<<grid, 256>>>(wgt, bias, out);
}

// round 4
// speedup vs baseline: 1.4298x; 1.4298x over previous
#include <cuda_runtime.h>
#include <cuda_bf16.h>
#include <cstdint>
#include <math.h>

#define N_    8
#define C_    256
#define H_    64
#define W_    64
#define K_    9
#define P_    4096          // 64*64
#define CK_   2304          // C_*K_
#define COUT_ 256

// ------------------------------- scratch ------------------------------------
// cols split to bf16 hi/lo, K-major layout [n][p][k*256+c]
__device__ __nv_bfloat16 g_chi[(size_t)N_ * P_ * CK_];
__device__ __nv_bfloat16 g_clo[(size_t)N_ * P_ * CK_];
// weights split + reordered to [cout][k*256+c]
__device__ __nv_bfloat16 g_whi[COUT_ * CK_];
__device__ __nv_bfloat16 g_wlo[COUT_ * CK_];

// ---------------- small PTX helpers (family-agnostic only) ------------------
__device__ __forceinline__ uint32_t smem_to_u32(const void* p) {
    uint32_t a;
    asm("{ .reg .u64 t; cvta.to.shared.u64 t, %1; cvt.u32.u64 %0, t; }"
        : "=r"(a) : "l"(p));
    return a;
}
__device__ __forceinline__ void cp16(uint32_t dst, const void* src) {
    asm volatile("cp.async.cg.shared.global [%0], [%1], 16;"
                 :: "r"(dst), "l"(src));
}
__device__ __forceinline__ void cp_commit() {
    asm volatile("cp.async.commit_group;" ::: "memory");
}
template <int NN>
__device__ __forceinline__ void cp_wait() {
    asm volatile("cp.async.wait_group %0;" :: "n"(NN) : "memory");
}
__device__ __forceinline__ void ldsm4(uint32_t* r, uint32_t addr) {
    asm volatile("ldmatrix.sync.aligned.m8n8.x4.shared.b16 {%0,%1,%2,%3}, [%4];"
        : "=r"(r[0]), "=r"(r[1]), "=r"(r[2]), "=r"(r[3]) : "r"(addr));
}
__device__ __forceinline__ void mma16816(float* d, const uint32_t* a,
                                         uint32_t b0, uint32_t b1) {
    asm volatile("mma.sync.aligned.m16n8k16.row.col.f32.bf16.bf16.f32 "
        "{%0,%1,%2,%3}, {%4,%5,%6,%7}, {%8,%9}, {%0,%1,%2,%3};"
        : "+f"(d[0]), "+f"(d[1]), "+f"(d[2]), "+f"(d[3])
        : "r"(a[0]), "r"(a[1]), "r"(a[2]), "r"(a[3]), "r"(b0), "r"(b1));
}

// ---------------------------------------------------------------------------
// Kernel 0: weight split + reorder: g_w[cout][k*256+c] = split(w[cout][c][k])
// ---------------------------------------------------------------------------
__global__ void wsplit_k(const float* __restrict__ w) {
    int o = blockIdx.x * 256 + threadIdx.x;
    if (o >= COUT_ * CK_) return;
    int cout = o / CK_;
    int r    = o % CK_;
    int k    = r >> 8;          // 0..8
    int c    = r & 255;
    float v = w[(size_t)cout * CK_ + c * 9 + k];
    __nv_bfloat16 hi = __float2bfloat16(v);
    float lo = v - __bfloat162float(hi);
    g_whi[o] = hi;
    g_wlo[o] = __float2bfloat16(lo);
}

// ---------------------------------------------------------------------------
// Kernel 1: deformable im2col -> bf16 hi/lo columns, K-major per pixel
// ---------------------------------------------------------------------------
__global__ void im2col_k(const float* __restrict__ x,
                         const float* __restrict__ off)
{
    int idx = blockIdx.x * blockDim.x + threadIdx.x;
    if (idx >= N_ * K_ * P_) return;

    int p  = idx & (P_ - 1);
    int nk = idx >> 12;
    int k  = nk % K_;
    int n  = nk / K_;
    int ho = p >> 6;
    int wo = p & 63;
    int ky = k / 3;
    int kx = k % 3;

    const float* ob = off + ((size_t)n * (2 * K_) + k * 2) * P_;
    float py = (float)(ho - 1 + ky) + ob[p];
    float px = (float)(wo - 1 + kx) + ob[P_ + p];

    float y0f = floorf(py), x0f = floorf(px);
    float ly = py - y0f, lx = px - x0f;
    float hy = 1.0f - ly, hx = 1.0f - lx;
    int y0 = (int)y0f, x0 = (int)x0f;
    int y1 = y0 + 1,   x1 = x0 + 1;

    bool vy0 = ((unsigned)y0 < (unsigned)H_);
    bool vy1 = ((unsigned)y1 < (unsigned)H_);
    bool vx0 = ((unsigned)x0 < (unsigned)W_);
    bool vx1 = ((unsigned)x1 < (unsigned)W_);

    int cy0 = min(max(y0, 0), H_ - 1);
    int cy1 = min(max(y1, 0), H_ - 1);
    int cx0 = min(max(x0, 0), W_ - 1);
    int cx1 = min(max(x1, 0), W_ - 1);

    float w00 = (vy0 && vx0) ? hy * hx : 0.0f;
    float w01 = (vy0 && vx1) ? hy * lx : 0.0f;
    float w10 = (vy1 && vx0) ? ly * hx : 0.0f;
    float w11 = (vy1 && vx1) ? ly * lx : 0.0f;

    int i00 = cy0 * W_ + cx0;
    int i01 = cy0 * W_ + cx1;
    int i10 = cy1 * W_ + cx0;
    int i11 = cy1 * W_ + cx1;

    const float* xb = x + (size_t)n * C_ * (H_ * W_);
    size_t obase = ((size_t)(n * P_ + p)) * CK_ + k * 256;

    union { __nv_bfloat16 h[8]; uint4 v; } bh, bl;
    for (int c8 = 0; c8 < 32; ++c8) {
        #pragma unroll
        for (int j = 0; j < 8; ++j) {
            const float* xc = xb + (size_t)(c8 * 8 + j) * (H_ * W_);
            float v = w00 * __ldg(xc + i00) + w01 * __ldg(xc + i01)
                    + w10 * __ldg(xc + i10) + w11 * __ldg(xc + i11);
            __nv_bfloat16 h = __float2bfloat16(v);
            bh.h[j] = h;
            bl.h[j] = __float2bfloat16(v - __bfloat162float(h));
        }
        *(uint4*)(g_chi + obase + c8 * 8) = bh.v;
        *(uint4*)(g_clo + obase + c8 * 8) = bl.v;
    }
}

// ---------------------------------------------------------------------------
// Kernel 2: mma.sync bf16x3 GEMM
// out[n][cout][p], D[cout, pixel] = W[cout, 2304] @ cols[pixel, 2304]^T
// CTA tile 128 cout x 128 pixels, K-chunk 32, 4-stage cp.async pipeline.
// ---------------------------------------------------------------------------
#define KC        32
#define NCHUNK    72            // 2304/32
#define PITCH     80            // smem row pitch bytes (64B data + 16B pad)
#define A_HI      0
#define A_LO      10240
#define B_HI      20480
#define B_LO      30720
#define STAGE     40960
#define NSTAGE    4
#define SMEM_TOTAL (NSTAGE * STAGE)   // 160 KB

__device__ __forceinline__ void load_stage(uint32_t st, int chunk,
                                           int cout0, int n, int p0, int tid)
{
    const size_t ckb = (size_t)chunk * (KC * 2);   // byte offset in 4608B row
    #pragma unroll
    for (int i = 0; i < 4; ++i) {                  // A = weights
        int idx = tid + i * 256;                   // 0..1023
        int row = idx >> 3;
        int rem = idx & 7;
        int c16 = rem & 3;
        int lo  = rem >> 2;
        const char* src = (const char*)(lo ? g_wlo : g_whi)
                        + (size_t)(cout0 + row) * (CK_ * 2) + ckb + c16 * 16;
        cp16(st + (lo ? A_LO : A_HI) + row * PITCH + c16 * 16, src);
    }
    #pragma unroll
    for (int i = 0; i < 4; ++i) {                  // B = cols
        int idx = tid + i * 256;
        int row = idx >> 3;
        int rem = idx & 7;
        int c16 = rem & 3;
        int lo  = rem >> 2;
        const char* src = (const char*)(lo ? g_clo : g_chi)
                        + ((size_t)(n * P_ + p0 + row)) * (CK_ * 2) + ckb + c16 * 16;
        cp16(st + (lo ? B_LO : B_HI) + row * PITCH + c16 * 16, src);
    }
}

__global__ __launch_bounds__(256)
void gemm_k(const float* __restrict__ bias, float* __restrict__ out)
{
    extern __shared__ __align__(128) char smem[];
    const uint32_t sb = smem_to_u32(smem);

    const int tid    = threadIdx.x;
    const int wid    = tid >> 5;
    const int lane   = tid & 31;
    const int warp_m = wid & 1;       // 0..1  (64-cout half)
    const int warp_n = wid >> 1;      // 0..3  (32-pixel quarter)

    const int cout0 = blockIdx.x * 128;
    const int p0    = blockIdx.y * 128;
    const int n     = blockIdx.z;

    float d[4][4][4];
    #pragma unroll
    for (int mi = 0; mi < 4; ++mi)
        #pragma unroll
        for (int ni = 0; ni < 4; ++ni)
            #pragma unroll
            for (int j = 0; j < 4; ++j) d[mi][ni][j] = 0.0f;

    // prologue: prefetch chunks 0..2
    #pragma unroll
    for (int s = 0; s < NSTAGE - 1; ++s) {
        load_stage(sb + s * STAGE, s, cout0, n, p0, tid);
        cp_commit();
    }

    // precomputed ldmatrix lane addressing
    const int a_row = (lane & 15);
    const int a_c16 = (lane >> 4) << 4;
    const int b_row = (lane & 7) + ((lane >> 4) << 3);
    const int b_c16 = ((lane >> 3) & 1) << 4;

    for (int c = 0; c < NCHUNK; ++c) {
        cp_wait<NSTAGE - 2>();
        __syncthreads();

        const uint32_t st = sb + (c & (NSTAGE - 1)) * STAGE;

        #pragma unroll
        for (int s = 0; s < 2; ++s) {           // two k16 steps per chunk
            uint32_t ah[4][4], al[4][4];
            #pragma unroll
            for (int mi = 0; mi < 4; ++mi) {
                uint32_t ra = st + A_HI
                            + (warp_m * 64 + mi * 16 + a_row) * PITCH
                            + s * 32 + a_c16;
                ldsm4(ah[mi], ra);
                ldsm4(al[mi], ra + (A_LO - A_HI));
            }
            uint32_t bhf[2][4], blf[2][4];
            #pragma unroll
            for (int np = 0; np < 2; ++np) {
                uint32_t rb = st + B_HI
                            + (warp_n * 32 + np * 16 + b_row) * PITCH
                            + s * 32 + b_c16;
                ldsm4(bhf[np], rb);
                ldsm4(blf[np], rb + (B_LO - B_HI));
            }
            #pragma unroll
            for (int mi = 0; mi < 4; ++mi)
                #pragma unroll
                for (int ni = 0; ni < 4; ++ni) {
                    const int np = ni >> 1, sub = (ni & 1) * 2;
                    uint32_t b0h = bhf[np][sub], b1h = bhf[np][sub + 1];
                    uint32_t b0l = blf[np][sub], b1l = blf[np][sub + 1];
                    mma16816(d[mi][ni], ah[mi], b0h, b1h);
                    mma16816(d[mi][ni], ah[mi], b0l, b1l);
                    mma16816(d[mi][ni], al[mi], b0h, b1h);
                }
        }

        __syncthreads();
        if (c + NSTAGE - 1 < NCHUNK)
            load_stage(sb + ((c + NSTAGE - 1) & (NSTAGE - 1)) * STAGE,
                       c + NSTAGE - 1, cout0, n, p0, tid);
        cp_commit();     // unconditional: keeps wait_group bookkeeping uniform
    }

    // epilogue: D fragment (row=cout, col=pixel) -> out[n][cout][p] + bias
    const int gr = lane >> 2;
    const int gc = (lane & 3) * 2;
    #pragma unroll
    for (int mi = 0; mi < 4; ++mi) {
        const int cout = cout0 + warp_m * 64 + mi * 16 + gr;
        const float bv0 = __ldg(bias + cout);
        const float bv1 = __ldg(bias + cout + 8);
        float* base = out + ((size_t)n * COUT_ + cout) * P_;
        #pragma unroll
        for (int ni = 0; ni < 4; ++ni) {
            const int px = p0 + warp_n * 32 + ni * 8 + gc;
            float2 v0 = make_float2(d[mi][ni][0] + bv0, d[mi][ni][1] + bv0);
            float2 v1 = make_float2(d[mi][ni][2] + bv1, d[mi][ni][3] + bv1);
            *(float2*)(base + px)            = v0;
            *(float2*)(base + 8 * P_ + px)   = v1;
        }
    }
}

// ---------------------------------------------------------------------------
extern "C" void kernel_launch(void* const* d_in, const int* in_sizes, int n_in,
                              void* d_out, int out_size)
{
    const float* x    = (const float*)d_in[0];
    const float* off  = (const float*)d_in[1];
    const float* wgt  = (const float*)d_in[2];
    const float* bias = (const float*)d_in[3];
    float* out = (float*)d_out;

    static bool attr_set = false;
    if (!attr_set) {
        cudaFuncSetAttribute(gemm_k, cudaFuncAttributeMaxDynamicSharedMemorySize,
                             SMEM_TOTAL);
        attr_set = true;
    }

    wsplit_k<<<(COUT_ * CK_ + 255) / 256, 256>>>(wgt);
    im2col_k<<<(N_ * K_ * P_) / 256, 256>>>(x, off);

    dim3 grid(COUT_ / 128, P_ / 128, N_);   // (2, 32, 8): cout-tiles adjacent
    gemm_k<<<grid, 256, SMEM_TOTAL>>>(bias, out);
}